// round 14
// baseline (speedup 1.0000x reference)
#include <cuda_runtime.h>
#include <cuda_bf16.h>

// Fused DCNv2 forward, 2 pixels/thread, channel-packed f32x2 conv accumulators
// ({y,x} offset pairs + mask pairs per pixel), constant-memory weights shared
// across the pixel pair (halves LDCU + window loads per pixel), deform loop
// with interior fast path (R13).

#define HH 512
#define WW 512
#define CC 3
#define OCC 27
#define KK 9
#define HW (HH * WW)

typedef unsigned long long u64;

// Per-g constant row (16 u64 = 128B):
//   j = 0..8 : {w_off[2k][g],   w_off[2k+1][g]}   (k = j)      offset pairs
//   j = 9..13: {w_off[18+2m][g], w_off[19+2m][g]} (m = j-9; m=4 hi = 0) masks
struct GBlob {
    u64   cG[27 * 16];
    float wdd[84];        // w_def [o*27 + c*9 + k]
    float boff[28];
    float bdef[4];
};

__constant__ GBlob c_b;
__device__   GBlob g_scratch;

__device__ __forceinline__ u64 pk2(float lo, float hi) {
    u64 r; asm("mov.b64 %0, {%1, %2};" : "=l"(r) : "f"(lo), "f"(hi)); return r;
}
__device__ __forceinline__ void upk2(u64 v, float& lo, float& hi) {
    asm("mov.b64 {%0, %1}, %2;" : "=f"(lo), "=f"(hi) : "l"(v));
}
__device__ __forceinline__ void ffma2(u64& acc, u64 a, u64 b) {
    asm("fma.rn.f32x2 %0, %1, %2, %0;" : "+l"(acc) : "l"(a), "l"(b));
}

__global__ void dcn_prep_kernel(const float* __restrict__ w_off,
                                const float* __restrict__ b_off,
                                const float* __restrict__ w_def,
                                const float* __restrict__ b_def)
{
    const int i = threadIdx.x;
    if (i < 27 * 16) {
        const int g = i >> 4, j = i & 15;
        u64 v = 0ull;
        if (j < 9) {
            v = pk2(w_off[(2 * j) * 27 + g], w_off[(2 * j + 1) * 27 + g]);
        } else if (j < 14) {
            const int m = j - 9;
            const float hi = (m < 4) ? w_off[(19 + 2 * m) * 27 + g] : 0.0f;
            v = pk2(w_off[(18 + 2 * m) * 27 + g], hi);
        }
        g_scratch.cG[i] = v;
    } else if (i < 432 + 84) {
        const int j = i - 432;
        g_scratch.wdd[j] = (j < 81) ? w_def[j] : 0.0f;
    } else if (i < 432 + 84 + 28) {
        const int j = i - 516;
        g_scratch.boff[j] = (j < OCC) ? b_off[j] : 0.0f;
    } else if (i < 432 + 84 + 32) {
        const int j = i - 544;
        g_scratch.bdef[j] = (j < 3) ? b_def[j] : 0.0f;
    }
}

// Deformable sampling + 3-channel mix for ONE pixel (fully unrolled; arrays
// must be compile-time indexed so everything stays in registers).
__device__ __forceinline__ void deform_px(
    const float* __restrict__ xb, int hI, int wI,
    const u64 oyx[9], const u64 om[5],
    float& acc0, float& acc1, float& acc2)
{
    float mz[10];
#pragma unroll
    for (int m = 0; m < 5; ++m) upk2(om[m], mz[2 * m], mz[2 * m + 1]);

#pragma unroll
    for (int k = 0; k < KK; ++k) {
        float oy, ox;
        upk2(oyx[k], oy, ox);
        const float py = (float)hI + (float)(k / 3 - 1) + oy;
        const float px = (float)wI + (float)(k % 3 - 1) + ox;
        const float m  = __fdividef(1.0f, 1.0f + __expf(-mz[k]));

        const float y0f = floorf(py);
        const float x0f = floorf(px);
        const float dy = py - y0f;
        const float dx = px - x0f;
        const int y0  = (int)y0f;
        const int x0i = (int)x0f;

        const float a  = (1.0f - dy) * m;
        const float bm = dy * m;
        const float w00 = a  * (1.0f - dx);
        const float w01 = a  * dx;
        const float w10 = bm * (1.0f - dx);
        const float w11 = bm * dx;

        const int i00 = y0 * WW + x0i;

        if ((unsigned)y0 < (unsigned)(HH - 1) && (unsigned)x0i < (unsigned)(WW - 1)) {
#pragma unroll
            for (int c = 0; c < CC; ++c) {
                const float* pc = xb + c * HW;
                const float v00 = __ldg(pc + i00);
                const float v01 = __ldg(pc + i00 + 1);
                const float v10 = __ldg(pc + i00 + WW);
                const float v11 = __ldg(pc + i00 + WW + 1);
                const float val = v00 * w00 + v01 * w01 + v10 * w10 + v11 * w11;
                acc0 = fmaf(c_b.wdd[0 * 27 + c * 9 + k], val, acc0);
                acc1 = fmaf(c_b.wdd[1 * 27 + c * 9 + k], val, acc1);
                acc2 = fmaf(c_b.wdd[2 * 27 + c * 9 + k], val, acc2);
            }
        } else {
            const bool y0v = ((unsigned)y0        < (unsigned)HH);
            const bool y1v = ((unsigned)(y0 + 1)  < (unsigned)HH);
            const bool x0v = ((unsigned)x0i       < (unsigned)WW);
            const bool x1v = ((unsigned)(x0i + 1) < (unsigned)WW);
#pragma unroll
            for (int c = 0; c < CC; ++c) {
                const float* pc = xb + c * HW;
                const float v00 = (y0v && x0v) ? __ldg(pc + i00)          : 0.0f;
                const float v01 = (y0v && x1v) ? __ldg(pc + i00 + 1)      : 0.0f;
                const float v10 = (y1v && x0v) ? __ldg(pc + i00 + WW)     : 0.0f;
                const float v11 = (y1v && x1v) ? __ldg(pc + i00 + WW + 1) : 0.0f;
                const float val = v00 * w00 + v01 * w01 + v10 * w10 + v11 * w11;
                acc0 = fmaf(c_b.wdd[0 * 27 + c * 9 + k], val, acc0);
                acc1 = fmaf(c_b.wdd[1 * 27 + c * 9 + k], val, acc1);
                acc2 = fmaf(c_b.wdd[2 * 27 + c * 9 + k], val, acc2);
            }
        }
    }
}

__global__ __launch_bounds__(128, 5)
void dcn_fused2_kernel(const float* __restrict__ x, float* __restrict__ out)
{
    // One thread = pixel pair (hI, wI), (hI, wI+1) with wI even.
    const int idx = blockIdx.x * blockDim.x + threadIdx.x;   // 0 .. 8*512*256-1
    const int wI = (idx & 255) << 1;
    const int hI = (idx >> 8) & (HH - 1);
    const int b  = idx >> 17;

    const float* xb = x + (size_t)b * CC * HW;

    // ---- conv accumulators for both pixels (channel-packed) ----
    u64 oyxA[9], omA[5], oyxB[9], omB[5];
#pragma unroll
    for (int k = 0; k < 9; ++k) {
        const u64 bv = pk2(c_b.boff[2 * k], c_b.boff[2 * k + 1]);
        oyxA[k] = bv; oyxB[k] = bv;
    }
#pragma unroll
    for (int m = 0; m < 5; ++m) {
        const u64 bv = pk2(c_b.boff[18 + 2 * m], (m < 4) ? c_b.boff[19 + 2 * m] : 0.0f);
        omA[m] = bv; omB[m] = bv;
    }

    // ---- conv: shared window + shared LDCU, both pixels ----
#pragma unroll
    for (int c = 0; c < CC; ++c) {
        const float* xc = xb + c * HW;
        float win[12];   // 3 rows x 4 cols (x = wI-1 .. wI+2); middle 2 are aligned
#pragma unroll
        for (int r = 0; r < 3; ++r) {
            const int y = hI + r - 1;
            const bool yv = ((unsigned)y < (unsigned)HH);
            const float* rowp = xc + y * WW;
            float2 mid = make_float2(0.0f, 0.0f);
            if (yv) mid = __ldg(reinterpret_cast<const float2*>(rowp + wI));
            win[r * 4 + 1] = mid.x;
            win[r * 4 + 2] = mid.y;
            win[r * 4 + 0] = (yv && wI > 0)      ? __ldg(rowp + wI - 1) : 0.0f;
            win[r * 4 + 3] = (yv && wI + 2 < WW) ? __ldg(rowp + wI + 2) : 0.0f;
        }
#pragma unroll
        for (int t = 0; t < 9; ++t) {
            const int ky = t / 3, kx = t % 3;
            const u64 vdA = pk2(win[ky * 4 + kx],     win[ky * 4 + kx]);
            const u64 vdB = pk2(win[ky * 4 + kx + 1], win[ky * 4 + kx + 1]);
            const int gbase = (c * 9 + t) * 16;   // compile-time after unroll
#pragma unroll
            for (int k = 0; k < 9; ++k) {
                const u64 wv = c_b.cG[gbase + k];
                ffma2(oyxA[k], wv, vdA);
                ffma2(oyxB[k], wv, vdB);
            }
#pragma unroll
            for (int m = 0; m < 5; ++m) {
                const u64 wv = c_b.cG[gbase + 9 + m];
                ffma2(omA[m], wv, vdA);
                ffma2(omB[m], wv, vdB);
            }
        }
    }

    // ---- deform both pixels ----
    float a0 = c_b.bdef[0], a1 = c_b.bdef[1], a2 = c_b.bdef[2];
    deform_px(xb, hI, wI, oyxA, omA, a0, a1, a2);
    float b0 = c_b.bdef[0], b1 = c_b.bdef[1], b2 = c_b.bdef[2];
    deform_px(xb, hI, wI + 1, oyxB, omB, b0, b1, b2);

    const size_t obase = (size_t)b * 3 * HW + (size_t)hI * WW + wI;
    *reinterpret_cast<float2*>(out + obase)          = make_float2(a0, b0);
    *reinterpret_cast<float2*>(out + obase + HW)     = make_float2(a1, b1);
    *reinterpret_cast<float2*>(out + obase + 2 * HW) = make_float2(a2, b2);
}

extern "C" void kernel_launch(void* const* d_in, const int* in_sizes, int n_in,
                              void* d_out, int out_size)
{
    const float* x     = (const float*)d_in[0];
    const float* w_off = (const float*)d_in[1];
    const float* b_off = (const float*)d_in[2];
    const float* w_def = (const float*)d_in[3];
    const float* b_def = (const float*)d_in[4];
    float* out = (float*)d_out;

    // 1) Build packed weight blob in device scratch.
    dcn_prep_kernel<<<1, 576>>>(w_off, b_off, w_def, b_def);

    // 2) Stage blob into __constant__ (one D2D copy).
    void* scratch_ptr = nullptr;
    cudaGetSymbolAddress(&scratch_ptr, g_scratch);
    cudaMemcpyToSymbolAsync(c_b, scratch_ptr, sizeof(GBlob), 0,
                            cudaMemcpyDeviceToDevice);

    // 3) Main fused kernel: 2 px/thread.
    const int totalPairs = 8 * 512 * 256;    // 1,048,576 pixel pairs
    dcn_fused2_kernel<<<totalPairs / 128, 128>>>(x, out);
}